// round 16
// baseline (speedup 1.0000x reference)
#include <cuda_runtime.h>
#include <cuda_bf16.h>
#include <math_constants.h>
#include <cstdint>

#define D      768
#define BPREV  8192
#define BCUR   4096
#define KNB    5
#define KCB    8           // candidates kept per (row, j-block)
#define KC2    16          // global candidates rescored in fp32
#define JBLK   64          // number of 128-wide j blocks (8192/128)
#define CPR    (JBLK * KCB)   // 512 candidates per row
#define KCHUNK 32          // K elements per pipeline chunk
#define NCHUNK (D / KCHUNK)   // 24
#define STAGES 4

// smem layout (bytes): A/B tiles padded to 80B per 64B row
#define SA        80
#define TILE_BYTES (128 * SA)            // 10240 (one of A or B)
#define STAGE_BYTES (2 * TILE_BYTES)     // 20480 (A then B)
#define SIM_STRIDE 132                   // floats
#define SMEM_KNN  (STAGES * STAGE_BYTES) // 81920 >= Sim (67584)

// ---------------- device scratch ----------------
__device__ float           g_hp[BPREV * D];     // normalized previous (fp32)
__device__ __nv_bfloat16   g_hp_bf[BPREV * D];  // normalized previous (bf16)
__device__ float           g_hc[BCUR * D];      // normalized current
__device__ float           g_sq[BCUR];
__device__ float g_cand_val[BCUR * CPR];
__device__ int   g_cand_idx[BCUR * CPR];
__device__ int   g_cand2[BCUR * KC2];

// ---------------- helpers ----------------
__device__ __forceinline__ uint32_t smem_to_u32(const void* p) {
    uint32_t a;
    asm("{ .reg .u64 t; cvta.to.shared.u64 t, %1; cvt.u32.u64 %0, t; }" : "=r"(a) : "l"(p));
    return a;
}
__device__ __forceinline__ bool better(float v1, int j1, float v2, int j2) {
    return (v1 > v2) || (v1 == v2 && j1 < j2);   // JAX top_k tie-break
}
template <int KK>
__device__ __forceinline__ void insertK(float v, int j, float* tv, int* tj) {
    if (!better(v, j, tv[KK - 1], tj[KK - 1])) return;
    tv[KK - 1] = v; tj[KK - 1] = j;
#pragma unroll
    for (int k = KK - 1; k > 0; --k) {
        if (better(tv[k], tj[k], tv[k - 1], tj[k - 1])) {
            float fv = tv[k]; tv[k] = tv[k - 1]; tv[k - 1] = fv;
            int   ij = tj[k]; tj[k] = tj[k - 1]; tj[k - 1] = ij;
        }
    }
}
// order-preserving (value desc, index asc) packing: bigger key = better
__device__ __forceinline__ unsigned long long pack_key(float v, int j) {
    uint32_t u = __float_as_uint(v);
    u = (u & 0x80000000u) ? ~u : (u | 0x80000000u);   // monotonic float->uint
    return ((unsigned long long)u << 32) | (uint32_t)(~j);
}

// bf16 mma: D(16x8,f32) += A(16x16,bf16 row) * B(8x16,bf16 col)
__device__ __forceinline__ void mma_bf16(float* d, const uint32_t* a,
                                         const uint32_t* b, const float* c) {
    asm volatile(
        "mma.sync.aligned.m16n8k16.row.col.f32.bf16.bf16.f32 "
        "{%0,%1,%2,%3}, {%4,%5,%6,%7}, {%8,%9}, {%10,%11,%12,%13};\n"
        : "=f"(d[0]), "=f"(d[1]), "=f"(d[2]), "=f"(d[3])
        : "r"(a[0]), "r"(a[1]), "r"(a[2]), "r"(a[3]),
          "r"(b[0]), "r"(b[1]),
          "f"(c[0]), "f"(c[1]), "f"(c[2]), "f"(c[3]));
}
#define LDMATRIX_X4(r0, r1, r2, r3, addr) \
    asm volatile("ldmatrix.sync.aligned.m8n8.x4.shared.b16 {%0,%1,%2,%3}, [%4];" \
        : "=r"(r0), "=r"(r1), "=r"(r2), "=r"(r3) : "r"(addr))
#define CP_ASYNC_16(dst, src) \
    asm volatile("cp.async.cg.shared.global [%0], [%1], 16;" :: "r"(dst), "l"(src))
#define CP_ASYNC_COMMIT() asm volatile("cp.async.commit_group;")
#define CP_ASYNC_WAIT(n)  asm volatile("cp.async.wait_group %0;" :: "n"(n))

// ---------------- small kernels ----------------
__global__ void zero_out(float* out) { out[0] = 0.0f; }

// one WARP per row; rows [0, BPREV) = previous, [BPREV, BPREV+BCUR) = current
__global__ void normalize_all(const float* __restrict__ prev,
                              const float* __restrict__ cur) {
    const int gw   = blockIdx.x * 8 + (threadIdx.x >> 5);
    const int lane = threadIdx.x & 31;
    const bool is_prev = gw < BPREV;
    const int r = is_prev ? gw : gw - BPREV;
    const float4* x4 = (const float4*)((is_prev ? prev : cur) + (size_t)r * D);

    float4 v[6];
    float s = 0.f;
#pragma unroll
    for (int q = 0; q < 6; q++) {
        v[q] = x4[lane + q * 32];
        s = fmaf(v[q].x, v[q].x, s); s = fmaf(v[q].y, v[q].y, s);
        s = fmaf(v[q].z, v[q].z, s); s = fmaf(v[q].w, v[q].w, s);
    }
#pragma unroll
    for (int off = 16; off; off >>= 1) s += __shfl_xor_sync(0xffffffffu, s, off);
    float rinv = 1.0f / fmaxf(sqrtf(s), 1e-12f);

    if (is_prev) {
        float4* dst = (float4*)(g_hp + (size_t)r * D);
        __nv_bfloat162* db = (__nv_bfloat162*)(g_hp_bf + (size_t)r * D);
#pragma unroll
        for (int q = 0; q < 6; q++) {
            float4 nv = make_float4(v[q].x * rinv, v[q].y * rinv,
                                    v[q].z * rinv, v[q].w * rinv);
            dst[lane + q * 32] = nv;
            int e2 = (lane + q * 32) * 2;
            db[e2]     = __floats2bfloat162_rn(nv.x, nv.y);
            db[e2 + 1] = __floats2bfloat162_rn(nv.z, nv.w);
        }
    } else {
        float4* dst = (float4*)(g_hc + (size_t)r * D);
        float s2 = 0.f;
#pragma unroll
        for (int q = 0; q < 6; q++) {
            float4 nv = make_float4(v[q].x * rinv, v[q].y * rinv,
                                    v[q].z * rinv, v[q].w * rinv);
            dst[lane + q * 32] = nv;
            s2 = fmaf(nv.x, nv.x, s2); s2 = fmaf(nv.y, nv.y, s2);
            s2 = fmaf(nv.z, nv.z, s2); s2 = fmaf(nv.w, nv.w, s2);
        }
#pragma unroll
        for (int off = 16; off; off >>= 1) s2 += __shfl_xor_sync(0xffffffffu, s2, off);
        if (lane == 0) g_sq[r] = s2;
    }
}

// ---------------- tensor-core kNN (bf16 mma.sync + ldmatrix + cp.async) ------
// grid (32, 64): 128 i-rows x 128 j-cols per CTA. 8 warps as 2(M) x 4(N).
__global__ void __launch_bounds__(256) knn_mma_kernel() {
    extern __shared__ char smem[];
    uint32_t smem_u32 = smem_to_u32(smem);
    const int tid    = threadIdx.x;
    const int wid    = tid >> 5;
    const int lane   = tid & 31;
    const int warp_m = wid >> 2;       // 0..1 -> rows warp_m*64
    const int warp_n = wid & 3;        // 0..3 -> cols warp_n*32
    const int i0 = blockIdx.x * 128;
    const int j0 = blockIdx.y * 128;

    float acc[4][4][4];
#pragma unroll
    for (int mf = 0; mf < 4; mf++)
#pragma unroll
        for (int nf = 0; nf < 4; nf++)
#pragma unroll
            for (int r = 0; r < 4; r++) acc[mf][nf][r] = 0.f;

    // staging: each thread copies 2x16B of A and 2x16B of B per chunk
    const int ld_row = tid >> 2;        // 0..63 (+64 for q=1)
    const int ld_c16 = tid & 3;
    const char* srcA0 = (const char*)&g_hp_bf[(size_t)(i0 + ld_row) * D + ld_c16 * 8];
    const char* srcA1 = (const char*)&g_hp_bf[(size_t)(i0 + 64 + ld_row) * D + ld_c16 * 8];
    const char* srcB0 = (const char*)&g_hp_bf[(size_t)(j0 + ld_row) * D + ld_c16 * 8];
    const char* srcB1 = (const char*)&g_hp_bf[(size_t)(j0 + 64 + ld_row) * D + ld_c16 * 8];
    const uint32_t dstA0 = smem_u32 + ld_row * SA + ld_c16 * 16;
    const uint32_t dstA1 = smem_u32 + (64 + ld_row) * SA + ld_c16 * 16;
    const uint32_t dstB0 = dstA0 + TILE_BYTES;
    const uint32_t dstB1 = dstA1 + TILE_BYTES;

    // ldmatrix lane-address components (constant across chunks)
    const int a_row_in  = (lane & 15);
    const int a_colbyte = (lane >> 4) * 16;
    const int b_row_in  = (lane & 7) + ((lane >> 4) << 3);
    const int b_colbyte = ((lane >> 3) & 1) * 16;
    const uint32_t aAddrBase = smem_u32 +
        (uint32_t)((warp_m * 64 + a_row_in) * SA + a_colbyte);
    const uint32_t bAddrBase = smem_u32 + TILE_BYTES +
        (uint32_t)((warp_n * 32 + b_row_in) * SA + b_colbyte);

    // prologue: issue first STAGES-1 chunks
#pragma unroll
    for (int s = 0; s < STAGES - 1; s++) {
        const uint32_t so = s * STAGE_BYTES;
        const size_t go = (size_t)s * KCHUNK * 2;   // bytes
        CP_ASYNC_16(dstA0 + so, srcA0 + go);
        CP_ASYNC_16(dstA1 + so, srcA1 + go);
        CP_ASYNC_16(dstB0 + so, srcB0 + go);
        CP_ASYNC_16(dstB1 + so, srcB1 + go);
        CP_ASYNC_COMMIT();
    }

    for (int c = 0; c < NCHUNK; c++) {
        CP_ASYNC_WAIT(STAGES - 2);
        __syncthreads();

        // issue chunk c+STAGES-1 FIRST (into stage last read at iter c-1),
        // so the async engine overlaps the compute below
        const int cn = c + STAGES - 1;
        if (cn < NCHUNK) {
            const uint32_t sn = (uint32_t)(cn & (STAGES - 1)) * STAGE_BYTES;
            const size_t gn = (size_t)cn * KCHUNK * 2;
            CP_ASYNC_16(dstA0 + sn, srcA0 + gn);
            CP_ASYNC_16(dstA1 + sn, srcA1 + gn);
            CP_ASYNC_16(dstB0 + sn, srcB0 + gn);
            CP_ASYNC_16(dstB1 + sn, srcB1 + gn);
        }
        CP_ASYNC_COMMIT();

        const uint32_t so = (uint32_t)(c & (STAGES - 1)) * STAGE_BYTES;
        uint32_t a[4][2][4];
        uint32_t b[2][4][2];
#pragma unroll
        for (int ks = 0; ks < 2; ks++) {
#pragma unroll
            for (int mf = 0; mf < 4; mf++) {
                uint32_t addr = aAddrBase + so + (uint32_t)(mf * 16 * SA + ks * 32);
                LDMATRIX_X4(a[mf][ks][0], a[mf][ks][1], a[mf][ks][2], a[mf][ks][3], addr);
            }
#pragma unroll
            for (int nf2 = 0; nf2 < 2; nf2++) {
                uint32_t addr = bAddrBase + so + (uint32_t)(nf2 * 16 * SA + ks * 32);
                LDMATRIX_X4(b[ks][nf2 * 2][0], b[ks][nf2 * 2][1],
                            b[ks][nf2 * 2 + 1][0], b[ks][nf2 * 2 + 1][1], addr);
            }
        }
#pragma unroll
        for (int ks = 0; ks < 2; ks++)
#pragma unroll
            for (int mf = 0; mf < 4; mf++)
#pragma unroll
                for (int nf = 0; nf < 4; nf++)
                    mma_bf16(acc[mf][nf], a[mf][ks], b[ks][nf], acc[mf][nf]);
    }
    CP_ASYNC_WAIT(0);
    __syncthreads();

    // stage sims to smem (reuses GEMM buffer space; mainloop fully drained)
    float* Sim = (float*)smem;
#pragma unroll
    for (int mf = 0; mf < 4; mf++) {
        int r0 = warp_m * 64 + mf * 16 + (lane >> 2);
#pragma unroll
        for (int nf = 0; nf < 4; nf++) {
            int c0 = warp_n * 32 + nf * 8 + (lane & 3) * 2;
            Sim[r0 * SIM_STRIDE + c0]           = acc[mf][nf][0];
            Sim[r0 * SIM_STRIDE + c0 + 1]       = acc[mf][nf][1];
            Sim[(r0 + 8) * SIM_STRIDE + c0]     = acc[mf][nf][2];
            Sim[(r0 + 8) * SIM_STRIDE + c0 + 1] = acc[mf][nf][3];
        }
    }
    __syncthreads();

    // scan: 2 threads per row, 64 cols each, keep top-8 per half
    const int row  = tid >> 1;
    const int half = tid & 1;
    const int ig   = i0 + row;
    float tv[KCB]; int tj[KCB];
#pragma unroll
    for (int k = 0; k < KCB; k++) { tv[k] = -CUDART_INF_F; tj[k] = 0x7fffffff; }
#pragma unroll 4
    for (int c0 = 0; c0 < 64; c0++) {
        int cc = half * 64 + c0;
        float v = Sim[row * SIM_STRIDE + cc];
        int jg = j0 + cc;
        if (jg != ig) insertK<KCB>(v, jg, tv, tj);
    }
    __syncthreads();
    // half 1 parks its list in smem scratch (Sim area is free now)
    float* scratch = (float*)smem;          // 128 rows x 16 slots
    if (half == 1) {
#pragma unroll
        for (int k = 0; k < KCB; k++) {
            scratch[row * 16 + k] = tv[k];
            ((int*)scratch)[row * 16 + 8 + k] = tj[k];
        }
    }
    __syncthreads();
    if (half == 0) {
#pragma unroll
        for (int k = 0; k < KCB; k++) {
            insertK<KCB>(scratch[row * 16 + k], ((int*)scratch)[row * 16 + 8 + k], tv, tj);
        }
        size_t base = ((size_t)ig * JBLK + blockIdx.y) * KCB;
#pragma unroll
        for (int k = 0; k < KCB; k++) {
            g_cand_val[base + k] = tv[k];
            g_cand_idx[base + k] = tj[k];
        }
    }
}

// merge 512 per-row candidates -> global top-16: one WARP per row.
// Candidates packed into order-preserving u64 keys; 16 butterfly-max pops.
__global__ void merge_kernel() {
    int row  = blockIdx.x * (blockDim.x >> 5) + (threadIdx.x >> 5);
    int lane = threadIdx.x & 31;
    if (row >= BCUR) return;

    size_t base = (size_t)row * CPR + (size_t)lane * 16;
    unsigned long long lk[8];
#pragma unroll
    for (int k = 0; k < 8; k++) lk[k] = 0ull;
#pragma unroll
    for (int q = 0; q < 4; q++) {
        float4 v4 = *(const float4*)&g_cand_val[base + q * 4];
        int4   j4 = *(const int4*)&g_cand_idx[base + q * 4];
        unsigned long long key[4] = {
            pack_key(v4.x, j4.x), pack_key(v4.y, j4.y),
            pack_key(v4.z, j4.z), pack_key(v4.w, j4.w) };
#pragma unroll
        for (int t = 0; t < 4; t++) {
            if (key[t] > lk[7]) {
                lk[7] = key[t];
#pragma unroll
                for (int k = 7; k > 0; --k)
                    if (lk[k] > lk[k - 1]) {
                        unsigned long long tmp = lk[k]; lk[k] = lk[k - 1]; lk[k - 1] = tmp;
                    }
            }
        }
    }
    int pos = 0;
    for (int k = 0; k < KC2; k++) {
        unsigned long long mine = (pos < 8) ? lk[pos] : 0ull;
        unsigned long long best = mine;
#pragma unroll
        for (int off = 16; off; off >>= 1) {
            unsigned long long o = __shfl_xor_sync(0xffffffffu, best, off);
            if (o > best) best = o;
        }
        if (lane == 0) g_cand2[row * KC2 + k] = (int)(~(uint32_t)best);
        if (mine == best) pos++;      // keys unique (idx unique): one lane advances
    }
}

// fused: fp32 rescore of 16 candidates, exact top-5 (JAX tie-break),
// then contribution accumulate. one block (512 threads) per row i.
__global__ void __launch_bounds__(512) rescore_contrib_kernel(
        const int* __restrict__ lprev, float* __restrict__ out) {
    int i = blockIdx.x;
    int w = threadIdx.x >> 5;
    int lane = threadIdx.x & 31;
    __shared__ float sv[KC2];
    __shared__ int   sj[KC2];
    __shared__ int   nbr[KNB];

    int j = g_cand2[i * KC2 + w];
    {
        const float4* xi = (const float4*)(g_hp + (size_t)i * D);
        const float4* xj = (const float4*)(g_hp + (size_t)j * D);
        float s = 0.f;
#pragma unroll
        for (int k = lane; k < D / 4; k += 32) {
            float4 a = xi[k], b = xj[k];
            s = fmaf(a.x, b.x, s); s = fmaf(a.y, b.y, s);
            s = fmaf(a.z, b.z, s); s = fmaf(a.w, b.w, s);
        }
#pragma unroll
        for (int off = 16; off; off >>= 1) s += __shfl_down_sync(0xffffffffu, s, off);
        if (lane == 0) { sv[w] = s; sj[w] = j; }
    }
    __syncthreads();
    if (threadIdx.x == 0) {
        bool used[KC2];
#pragma unroll
        for (int c = 0; c < KC2; c++) used[c] = false;
        for (int k = 0; k < KNB; k++) {
            int best = -1;
            for (int c = 0; c < KC2; c++) {
                if (used[c]) continue;
                if (best < 0 || better(sv[c], sj[c], sv[best], sj[best])) best = c;
            }
            used[best] = true;
            nbr[k] = sj[best];
        }
    }
    __syncthreads();
    if (w < KNB) {
        int jn = nbr[w];
        if (jn < BCUR) {   // only affinity[:4096,:4096] contributes
            const float4* xi = (const float4*)(g_hc + (size_t)i * D);
            const float4* xj = (const float4*)(g_hc + (size_t)jn * D);
            float s = 0.f;
#pragma unroll
            for (int k = lane; k < D / 4; k += 32) {
                float4 a = xi[k], b = xj[k];
                s = fmaf(a.x, b.x, s); s = fmaf(a.y, b.y, s);
                s = fmaf(a.z, b.z, s); s = fmaf(a.w, b.w, s);
            }
#pragma unroll
            for (int off = 16; off; off >>= 1) s += __shfl_down_sync(0xffffffffu, s, off);
            if (lane == 0) {
                float d2 = fmaxf(g_sq[i] + g_sq[jn] - 2.f * s, 0.f);
                float e = (lprev[i] == lprev[jn]) ? 1.f : -1.f;
                const float scale = 0.5f / ((float)BCUR * (float)BCUR);  // WEIGHT / B^2
                atomicAdd(out, e * d2 * scale);
            }
        }
    }
}

// ---------------- launcher ----------------
extern "C" void kernel_launch(void* const* d_in, const int* in_sizes, int n_in,
                              void* d_out, int out_size) {
    const float* hidden_current  = (const float*)d_in[0];   // 4096*768
    const float* hidden_previous = (const float*)d_in[1];   // 8192*768
    const int* labels_previous   = (const int*)d_in[3];     // int32 (jax x64 off)
    float* out = (float*)d_out;

    cudaFuncSetAttribute(knn_mma_kernel,
                         cudaFuncAttributeMaxDynamicSharedMemorySize, SMEM_KNN);

    zero_out<<<1, 1>>>(out);
    normalize_all<<<(BPREV + BCUR) / 8, 256>>>(hidden_previous, hidden_current);
    knn_mma_kernel<<<dim3(BCUR / 128, BPREV / 128), 256, SMEM_KNN>>>();
    merge_kernel<<<(BCUR * 32 + 255) / 256, 256>>>();
    rescore_contrib_kernel<<<BCUR, 512>>>(labels_previous, out);
}

// round 17
// speedup vs baseline: 1.4714x; 1.4714x over previous
#include <cuda_runtime.h>
#include <cuda_bf16.h>
#include <math_constants.h>
#include <cstdint>

#define D      768
#define BPREV  8192
#define BCUR   4096
#define KNB    5
#define KCB    8           // candidates kept per (row, j-block)
#define KC2    16          // global candidates rescored in fp32
#define JBLK   64          // number of 128-wide j blocks (8192/128)
#define CPR    (JBLK * KCB)   // 512 candidates per row
#define KCHUNK 32          // K elements per pipeline chunk
#define NCHUNK (D / KCHUNK)   // 24
#define STAGES 4

// smem layout (bytes): A/B tiles padded to 80B per 64B row
#define SA        80
#define TILE_BYTES (128 * SA)            // 10240 (one of A or B)
#define STAGE_BYTES (2 * TILE_BYTES)     // 20480 (A then B)
#define SIM_STRIDE 132                   // floats
#define SMEM_KNN  (STAGES * STAGE_BYTES) // 81920 >= Sim (67584)

// ---------------- device scratch ----------------
__device__ float           g_hp[BPREV * D];     // normalized previous (fp32)
__device__ __nv_bfloat16   g_hp_bf[BPREV * D];  // normalized previous (bf16)
__device__ float           g_hc[BCUR * D];      // normalized current
__device__ float           g_sq[BCUR];
__device__ float g_cand_val[BCUR * CPR];
__device__ int   g_cand_idx[BCUR * CPR];
__device__ int   g_cand2[BCUR * KC2];
__device__ int   g_nbr[BCUR * KNB];

// ---------------- helpers ----------------
__device__ __forceinline__ uint32_t smem_to_u32(const void* p) {
    uint32_t a;
    asm("{ .reg .u64 t; cvta.to.shared.u64 t, %1; cvt.u32.u64 %0, t; }" : "=r"(a) : "l"(p));
    return a;
}
__device__ __forceinline__ bool better(float v1, int j1, float v2, int j2) {
    return (v1 > v2) || (v1 == v2 && j1 < j2);   // JAX top_k tie-break
}
template <int KK>
__device__ __forceinline__ void insertK(float v, int j, float* tv, int* tj) {
    if (!better(v, j, tv[KK - 1], tj[KK - 1])) return;
    tv[KK - 1] = v; tj[KK - 1] = j;
#pragma unroll
    for (int k = KK - 1; k > 0; --k) {
        if (better(tv[k], tj[k], tv[k - 1], tj[k - 1])) {
            float fv = tv[k]; tv[k] = tv[k - 1]; tv[k - 1] = fv;
            int   ij = tj[k]; tj[k] = tj[k - 1]; tj[k - 1] = ij;
        }
    }
}
// order-preserving (value desc, index asc) packing: bigger key = better
__device__ __forceinline__ unsigned long long pack_key(float v, int j) {
    uint32_t u = __float_as_uint(v);
    u = (u & 0x80000000u) ? ~u : (u | 0x80000000u);   // monotonic float->uint
    return ((unsigned long long)u << 32) | (uint32_t)(~j);
}

// bf16 mma: D(16x8,f32) += A(16x16,bf16 row) * B(8x16,bf16 col)
__device__ __forceinline__ void mma_bf16(float* d, const uint32_t* a,
                                         const uint32_t* b, const float* c) {
    asm volatile(
        "mma.sync.aligned.m16n8k16.row.col.f32.bf16.bf16.f32 "
        "{%0,%1,%2,%3}, {%4,%5,%6,%7}, {%8,%9}, {%10,%11,%12,%13};\n"
        : "=f"(d[0]), "=f"(d[1]), "=f"(d[2]), "=f"(d[3])
        : "r"(a[0]), "r"(a[1]), "r"(a[2]), "r"(a[3]),
          "r"(b[0]), "r"(b[1]),
          "f"(c[0]), "f"(c[1]), "f"(c[2]), "f"(c[3]));
}
#define LDMATRIX_X4(r0, r1, r2, r3, addr) \
    asm volatile("ldmatrix.sync.aligned.m8n8.x4.shared.b16 {%0,%1,%2,%3}, [%4];" \
        : "=r"(r0), "=r"(r1), "=r"(r2), "=r"(r3) : "r"(addr))
#define CP_ASYNC_16(dst, src) \
    asm volatile("cp.async.cg.shared.global [%0], [%1], 16;" :: "r"(dst), "l"(src))
#define CP_ASYNC_COMMIT() asm volatile("cp.async.commit_group;")
#define CP_ASYNC_WAIT(n)  asm volatile("cp.async.wait_group %0;" :: "n"(n))

// ---------------- small kernels ----------------
__global__ void zero_out(float* out) { out[0] = 0.0f; }

// one WARP per row; rows [0, BPREV) = previous, [BPREV, BPREV+BCUR) = current
__global__ void normalize_all(const float* __restrict__ prev,
                              const float* __restrict__ cur) {
    const int gw   = blockIdx.x * 8 + (threadIdx.x >> 5);
    const int lane = threadIdx.x & 31;
    const bool is_prev = gw < BPREV;
    const int r = is_prev ? gw : gw - BPREV;
    const float4* x4 = (const float4*)((is_prev ? prev : cur) + (size_t)r * D);

    float4 v[6];
    float s = 0.f;
#pragma unroll
    for (int q = 0; q < 6; q++) {
        v[q] = x4[lane + q * 32];
        s = fmaf(v[q].x, v[q].x, s); s = fmaf(v[q].y, v[q].y, s);
        s = fmaf(v[q].z, v[q].z, s); s = fmaf(v[q].w, v[q].w, s);
    }
#pragma unroll
    for (int off = 16; off; off >>= 1) s += __shfl_xor_sync(0xffffffffu, s, off);
    float rinv = 1.0f / fmaxf(sqrtf(s), 1e-12f);

    if (is_prev) {
        float4* dst = (float4*)(g_hp + (size_t)r * D);
        __nv_bfloat162* db = (__nv_bfloat162*)(g_hp_bf + (size_t)r * D);
#pragma unroll
        for (int q = 0; q < 6; q++) {
            float4 nv = make_float4(v[q].x * rinv, v[q].y * rinv,
                                    v[q].z * rinv, v[q].w * rinv);
            dst[lane + q * 32] = nv;
            int e2 = (lane + q * 32) * 2;
            db[e2]     = __floats2bfloat162_rn(nv.x, nv.y);
            db[e2 + 1] = __floats2bfloat162_rn(nv.z, nv.w);
        }
    } else {
        float4* dst = (float4*)(g_hc + (size_t)r * D);
        float s2 = 0.f;
#pragma unroll
        for (int q = 0; q < 6; q++) {
            float4 nv = make_float4(v[q].x * rinv, v[q].y * rinv,
                                    v[q].z * rinv, v[q].w * rinv);
            dst[lane + q * 32] = nv;
            s2 = fmaf(nv.x, nv.x, s2); s2 = fmaf(nv.y, nv.y, s2);
            s2 = fmaf(nv.z, nv.z, s2); s2 = fmaf(nv.w, nv.w, s2);
        }
#pragma unroll
        for (int off = 16; off; off >>= 1) s2 += __shfl_xor_sync(0xffffffffu, s2, off);
        if (lane == 0) g_sq[r] = s2;
    }
}

// ---------------- tensor-core kNN (bf16 mma.sync + ldmatrix + cp.async) ------
// grid (32, 64): 128 i-rows x 128 j-cols per CTA. 8 warps as 2(M) x 4(N).
// EXACT R12 mainloop ordering: compute first, issue next chunk after.
__global__ void __launch_bounds__(256) knn_mma_kernel() {
    extern __shared__ char smem[];
    uint32_t smem_u32 = smem_to_u32(smem);
    const int tid    = threadIdx.x;
    const int wid    = tid >> 5;
    const int lane   = tid & 31;
    const int warp_m = wid >> 2;       // 0..1 -> rows warp_m*64
    const int warp_n = wid & 3;        // 0..3 -> cols warp_n*32
    const int i0 = blockIdx.x * 128;
    const int j0 = blockIdx.y * 128;

    float acc[4][4][4];
#pragma unroll
    for (int mf = 0; mf < 4; mf++)
#pragma unroll
        for (int nf = 0; nf < 4; nf++)
#pragma unroll
            for (int r = 0; r < 4; r++) acc[mf][nf][r] = 0.f;

    // staging: each thread copies 2x16B of A and 2x16B of B per chunk
    const int ld_row = tid >> 2;        // 0..63 (+64 for q=1)
    const int ld_c16 = tid & 3;
    const char* srcA0 = (const char*)&g_hp_bf[(size_t)(i0 + ld_row) * D + ld_c16 * 8];
    const char* srcA1 = (const char*)&g_hp_bf[(size_t)(i0 + 64 + ld_row) * D + ld_c16 * 8];
    const char* srcB0 = (const char*)&g_hp_bf[(size_t)(j0 + ld_row) * D + ld_c16 * 8];
    const char* srcB1 = (const char*)&g_hp_bf[(size_t)(j0 + 64 + ld_row) * D + ld_c16 * 8];
    const uint32_t dstA0 = smem_u32 + ld_row * SA + ld_c16 * 16;
    const uint32_t dstA1 = smem_u32 + (64 + ld_row) * SA + ld_c16 * 16;
    const uint32_t dstB0 = dstA0 + TILE_BYTES;
    const uint32_t dstB1 = dstA1 + TILE_BYTES;

    // ldmatrix lane-address components (constant across chunks)
    const int a_row_in  = (lane & 15);
    const int a_colbyte = (lane >> 4) * 16;
    const int b_row_in  = (lane & 7) + ((lane >> 4) << 3);
    const int b_colbyte = ((lane >> 3) & 1) * 16;
    const uint32_t aAddrBase = smem_u32 +
        (uint32_t)((warp_m * 64 + a_row_in) * SA + a_colbyte);
    const uint32_t bAddrBase = smem_u32 + TILE_BYTES +
        (uint32_t)((warp_n * 32 + b_row_in) * SA + b_colbyte);

    // prologue: issue first STAGES-1 chunks
#pragma unroll
    for (int s = 0; s < STAGES - 1; s++) {
        const uint32_t so = s * STAGE_BYTES;
        const size_t go = (size_t)s * KCHUNK * 2;   // bytes
        CP_ASYNC_16(dstA0 + so, srcA0 + go);
        CP_ASYNC_16(dstA1 + so, srcA1 + go);
        CP_ASYNC_16(dstB0 + so, srcB0 + go);
        CP_ASYNC_16(dstB1 + so, srcB1 + go);
        CP_ASYNC_COMMIT();
    }

    for (int c = 0; c < NCHUNK; c++) {
        CP_ASYNC_WAIT(STAGES - 2);
        __syncthreads();

        const uint32_t so = (uint32_t)(c & (STAGES - 1)) * STAGE_BYTES;
        uint32_t a[4][2][4];
        uint32_t b[2][4][2];
#pragma unroll
        for (int ks = 0; ks < 2; ks++) {
#pragma unroll
            for (int mf = 0; mf < 4; mf++) {
                uint32_t addr = aAddrBase + so + (uint32_t)(mf * 16 * SA + ks * 32);
                LDMATRIX_X4(a[mf][ks][0], a[mf][ks][1], a[mf][ks][2], a[mf][ks][3], addr);
            }
#pragma unroll
            for (int nf2 = 0; nf2 < 2; nf2++) {
                uint32_t addr = bAddrBase + so + (uint32_t)(nf2 * 16 * SA + ks * 32);
                LDMATRIX_X4(b[ks][nf2 * 2][0], b[ks][nf2 * 2][1],
                            b[ks][nf2 * 2 + 1][0], b[ks][nf2 * 2 + 1][1], addr);
            }
        }
#pragma unroll
        for (int ks = 0; ks < 2; ks++)
#pragma unroll
            for (int mf = 0; mf < 4; mf++)
#pragma unroll
                for (int nf = 0; nf < 4; nf++)
                    mma_bf16(acc[mf][nf], a[mf][ks], b[ks][nf], acc[mf][nf]);

        // issue chunk c+STAGES-1 into the stage just freed (prev iter's stage)
        const int cn = c + STAGES - 1;
        if (cn < NCHUNK) {
            const uint32_t sn = (uint32_t)(cn & (STAGES - 1)) * STAGE_BYTES;
            const size_t gn = (size_t)cn * KCHUNK * 2;
            CP_ASYNC_16(dstA0 + sn, srcA0 + gn);
            CP_ASYNC_16(dstA1 + sn, srcA1 + gn);
            CP_ASYNC_16(dstB0 + sn, srcB0 + gn);
            CP_ASYNC_16(dstB1 + sn, srcB1 + gn);
        }
        CP_ASYNC_COMMIT();
    }
    CP_ASYNC_WAIT(0);
    __syncthreads();

    // stage sims to smem (reuses GEMM buffer space; mainloop fully drained)
    float* Sim = (float*)smem;
#pragma unroll
    for (int mf = 0; mf < 4; mf++) {
        int r0 = warp_m * 64 + mf * 16 + (lane >> 2);
#pragma unroll
        for (int nf = 0; nf < 4; nf++) {
            int c0 = warp_n * 32 + nf * 8 + (lane & 3) * 2;
            Sim[r0 * SIM_STRIDE + c0]           = acc[mf][nf][0];
            Sim[r0 * SIM_STRIDE + c0 + 1]       = acc[mf][nf][1];
            Sim[(r0 + 8) * SIM_STRIDE + c0]     = acc[mf][nf][2];
            Sim[(r0 + 8) * SIM_STRIDE + c0 + 1] = acc[mf][nf][3];
        }
    }
    __syncthreads();

    // scan: 2 threads per row, 64 cols each, keep top-8 per half
    const int row  = tid >> 1;
    const int half = tid & 1;
    const int ig   = i0 + row;
    float tv[KCB]; int tj[KCB];
#pragma unroll
    for (int k = 0; k < KCB; k++) { tv[k] = -CUDART_INF_F; tj[k] = 0x7fffffff; }
#pragma unroll 4
    for (int c0 = 0; c0 < 64; c0++) {
        int cc = half * 64 + c0;
        float v = Sim[row * SIM_STRIDE + cc];
        int jg = j0 + cc;
        if (jg != ig) insertK<KCB>(v, jg, tv, tj);
    }
    __syncthreads();
    // half 1 parks its list in smem scratch (Sim area is free now)
    float* scratch = (float*)smem;          // 128 rows x 16 slots
    if (half == 1) {
#pragma unroll
        for (int k = 0; k < KCB; k++) {
            scratch[row * 16 + k] = tv[k];
            ((int*)scratch)[row * 16 + 8 + k] = tj[k];
        }
    }
    __syncthreads();
    if (half == 0) {
#pragma unroll
        for (int k = 0; k < KCB; k++) {
            insertK<KCB>(scratch[row * 16 + k], ((int*)scratch)[row * 16 + 8 + k], tv, tj);
        }
        size_t base = ((size_t)ig * JBLK + blockIdx.y) * KCB;
#pragma unroll
        for (int k = 0; k < KCB; k++) {
            g_cand_val[base + k] = tv[k];
            g_cand_idx[base + k] = tj[k];
        }
    }
}

// merge 512 per-row candidates -> global top-16: one WARP per row.
// Candidates packed into order-preserving u64 keys; 16 butterfly-max pops.
__global__ void merge_kernel() {
    int row  = blockIdx.x * (blockDim.x >> 5) + (threadIdx.x >> 5);
    int lane = threadIdx.x & 31;
    if (row >= BCUR) return;

    size_t base = (size_t)row * CPR + (size_t)lane * 16;
    unsigned long long lk[8];
#pragma unroll
    for (int k = 0; k < 8; k++) lk[k] = 0ull;
#pragma unroll
    for (int q = 0; q < 4; q++) {
        float4 v4 = *(const float4*)&g_cand_val[base + q * 4];
        int4   j4 = *(const int4*)&g_cand_idx[base + q * 4];
        unsigned long long key[4] = {
            pack_key(v4.x, j4.x), pack_key(v4.y, j4.y),
            pack_key(v4.z, j4.z), pack_key(v4.w, j4.w) };
#pragma unroll
        for (int t = 0; t < 4; t++) {
            if (key[t] > lk[7]) {
                lk[7] = key[t];
#pragma unroll
                for (int k = 7; k > 0; --k)
                    if (lk[k] > lk[k - 1]) {
                        unsigned long long tmp = lk[k]; lk[k] = lk[k - 1]; lk[k - 1] = tmp;
                    }
            }
        }
    }
    int pos = 0;
    for (int k = 0; k < KC2; k++) {
        unsigned long long mine = (pos < 8) ? lk[pos] : 0ull;
        unsigned long long best = mine;
#pragma unroll
        for (int off = 16; off; off >>= 1) {
            unsigned long long o = __shfl_xor_sync(0xffffffffu, best, off);
            if (o > best) best = o;
        }
        if (lane == 0) g_cand2[row * KC2 + k] = (int)(~(uint32_t)best);
        if (mine == best) pos++;      // keys unique (idx unique): one lane advances
    }
}

// fp32 rescore of 16 candidates per row; exact top-5 with JAX tie-break
__global__ void __launch_bounds__(512) rescore_kernel() {
    int i = blockIdx.x;
    int w = threadIdx.x >> 5;
    int lane = threadIdx.x & 31;
    __shared__ float sv[KC2];
    __shared__ int   sj[KC2];
    int j = g_cand2[i * KC2 + w];
    const float4* xi = (const float4*)(g_hp + (size_t)i * D);
    const float4* xj = (const float4*)(g_hp + (size_t)j * D);
    float s = 0.f;
#pragma unroll
    for (int k = lane; k < D / 4; k += 32) {
        float4 a = xi[k], b = xj[k];
        s = fmaf(a.x, b.x, s); s = fmaf(a.y, b.y, s);
        s = fmaf(a.z, b.z, s); s = fmaf(a.w, b.w, s);
    }
#pragma unroll
    for (int off = 16; off; off >>= 1) s += __shfl_down_sync(0xffffffffu, s, off);
    if (lane == 0) { sv[w] = s; sj[w] = j; }
    __syncthreads();
    if (threadIdx.x == 0) {
        bool used[KC2];
#pragma unroll
        for (int c = 0; c < KC2; c++) used[c] = false;
        for (int k = 0; k < KNB; k++) {
            int best = -1;
            for (int c = 0; c < KC2; c++) {
                if (used[c]) continue;
                if (best < 0 || better(sv[c], sj[c], sv[best], sj[best])) best = c;
            }
            used[best] = true;
            g_nbr[i * KNB + k] = sj[best];
        }
    }
}

// one block per row i; warp w handles neighbor w (labels are int32 on-device)
__global__ void contrib_kernel(const int* __restrict__ lprev,
                               float* __restrict__ out) {
    int i = blockIdx.x;
    int w = threadIdx.x >> 5;
    int lane = threadIdx.x & 31;
    if (w >= KNB) return;
    int j = g_nbr[i * KNB + w];
    if (j >= BCUR) return;   // only affinity[:4096,:4096] contributes
    const float4* xi = (const float4*)(g_hc + (size_t)i * D);
    const float4* xj = (const float4*)(g_hc + (size_t)j * D);
    float s = 0.f;
#pragma unroll
    for (int k = lane; k < D / 4; k += 32) {
        float4 a = xi[k], b = xj[k];
        s = fmaf(a.x, b.x, s); s = fmaf(a.y, b.y, s);
        s = fmaf(a.z, b.z, s); s = fmaf(a.w, b.w, s);
    }
#pragma unroll
    for (int off = 16; off; off >>= 1) s += __shfl_down_sync(0xffffffffu, s, off);
    if (lane == 0) {
        float d2 = fmaxf(g_sq[i] + g_sq[j] - 2.f * s, 0.f);
        float e = (lprev[i] == lprev[j]) ? 1.f : -1.f;
        const float scale = 0.5f / ((float)BCUR * (float)BCUR);  // WEIGHT / B^2
        atomicAdd(out, e * d2 * scale);
    }
}

// ---------------- launcher ----------------
extern "C" void kernel_launch(void* const* d_in, const int* in_sizes, int n_in,
                              void* d_out, int out_size) {
    const float* hidden_current  = (const float*)d_in[0];   // 4096*768
    const float* hidden_previous = (const float*)d_in[1];   // 8192*768
    const int* labels_previous   = (const int*)d_in[3];     // int32 (jax x64 off)
    float* out = (float*)d_out;

    cudaFuncSetAttribute(knn_mma_kernel,
                         cudaFuncAttributeMaxDynamicSharedMemorySize, SMEM_KNN);

    zero_out<<<1, 1>>>(out);
    normalize_all<<<(BPREV + BCUR) / 8, 256>>>(hidden_previous, hidden_current);
    knn_mma_kernel<<<dim3(BCUR / 128, BPREV / 128), 256, SMEM_KNN>>>();
    merge_kernel<<<(BCUR * 32 + 255) / 256, 256>>>();
    rescore_kernel<<<BCUR, KC2 * 32>>>();
    contrib_kernel<<<BCUR, KNB * 32>>>(labels_previous, out);
}